// round 1
// baseline (speedup 1.0000x reference)
#include <cuda_runtime.h>
#include <math.h>

// SphereConv: out[2,B,F,L,M] from x[B,1,C,L,M] (complex as 2 arrays) and
// w[F,C,N,1] (complex), weights linearly interpolated N=64 -> L=256 along l,
// channel-mean, sqrt(1+l) scale, relu on real part.
namespace {

constexpr int B = 4, C = 32, L = 256, M = 256, F = 8, N = 64;
constexpr int THREADS = 64;          // each thread owns 4 m's (float4)
constexpr int CSTRIDE4 = L * M / 4;  // float4 stride between channels

__global__ __launch_bounds__(THREADS)
void sphere_conv_kernel(const float* __restrict__ xr,
                        const float* __restrict__ xi,
                        const float* __restrict__ wr,
                        const float* __restrict__ wi,
                        float* __restrict__ out)
{
    const int bl = blockIdx.x;
    const int b  = bl >> 8;        // bl / L
    const int l  = bl & (L - 1);   // bl % L

    // Interpolated weights for this l, laid out [c][f] so 4 f's load as float4.
    __shared__ float swr[C * F];
    __shared__ float swi[C * F];

    const int tid = threadIdx.x;

    {
        // t = l/(L-1) * (N-1)  (match reference op order)
        float t  = ((float)l / (float)(L - 1)) * (float)(N - 1);
        int   lo = (int)floorf(t);
        lo = lo < 0 ? 0 : (lo > N - 2 ? N - 2 : lo);
        float frac = t - (float)lo;
        // fold mean (1/C) and scale sqrt(1+l) into the weights
        float sc = sqrtf(1.0f + (float)l) * (1.0f / (float)C);
        for (int i = tid; i < C * F; i += THREADS) {
            int c = i >> 3;   // i / F
            int f = i & 7;    // i % F
            int widx = (f * C + c) * N + lo;
            swr[i] = (wr[widx] * (1.0f - frac) + wr[widx + 1] * frac) * sc;
            swi[i] = (wi[widx] * (1.0f - frac) + wi[widx + 1] * frac) * sc;
        }
    }
    __syncthreads();

    const int m4 = tid;  // float4 index within the row of M=256
    const size_t base4 = ((size_t)b * C * L + l) * (M / 4) + m4;
    const float4* xr4 = reinterpret_cast<const float4*>(xr) + base4;
    const float4* xi4 = reinterpret_cast<const float4*>(xi) + base4;

    float4 ar[F], ai[F];
#pragma unroll
    for (int f = 0; f < F; ++f) {
        ar[f] = make_float4(0.f, 0.f, 0.f, 0.f);
        ai[f] = make_float4(0.f, 0.f, 0.f, 0.f);
    }

    const float4* swr4 = reinterpret_cast<const float4*>(swr);
    const float4* swi4 = reinterpret_cast<const float4*>(swi);

#pragma unroll 4
    for (int c = 0; c < C; ++c) {
        float4 vr = xr4[c * CSTRIDE4];
        float4 vi = xi4[c * CSTRIDE4];
        float4 w0 = swr4[c * 2 + 0];
        float4 w1 = swr4[c * 2 + 1];
        float4 u0 = swi4[c * 2 + 0];
        float4 u1 = swi4[c * 2 + 1];
        float wv[8] = {w0.x, w0.y, w0.z, w0.w, w1.x, w1.y, w1.z, w1.w};
        float uv[8] = {u0.x, u0.y, u0.z, u0.w, u1.x, u1.y, u1.z, u1.w};
#pragma unroll
        for (int f = 0; f < F; ++f) {
            float a = wv[f];
            float bb = uv[f];
            // real: += a*xr - bb*xi ; imag: += a*xi + bb*xr
            ar[f].x = fmaf(a, vr.x, fmaf(-bb, vi.x, ar[f].x));
            ar[f].y = fmaf(a, vr.y, fmaf(-bb, vi.y, ar[f].y));
            ar[f].z = fmaf(a, vr.z, fmaf(-bb, vi.z, ar[f].z));
            ar[f].w = fmaf(a, vr.w, fmaf(-bb, vi.w, ar[f].w));
            ai[f].x = fmaf(a, vi.x, fmaf( bb, vr.x, ai[f].x));
            ai[f].y = fmaf(a, vi.y, fmaf( bb, vr.y, ai[f].y));
            ai[f].z = fmaf(a, vi.z, fmaf( bb, vr.z, ai[f].z));
            ai[f].w = fmaf(a, vi.w, fmaf( bb, vr.w, ai[f].w));
        }
    }

    // out shape (2, B, F, L, M); real part gets relu.
    float4* out4 = reinterpret_cast<float4*>(out);
#pragma unroll
    for (int f = 0; f < F; ++f) {
        float4 r = ar[f];
        r.x = fmaxf(r.x, 0.f);
        r.y = fmaxf(r.y, 0.f);
        r.z = fmaxf(r.z, 0.f);
        r.w = fmaxf(r.w, 0.f);
        size_t or4 = (((size_t)(0 * B + b) * F + f) * L + l) * (M / 4) + m4;
        size_t oi4 = (((size_t)(1 * B + b) * F + f) * L + l) * (M / 4) + m4;
        out4[or4] = r;
        out4[oi4] = ai[f];
    }
}

}  // namespace

extern "C" void kernel_launch(void* const* d_in, const int* in_sizes, int n_in,
                              void* d_out, int out_size)
{
    const float* xr = (const float*)d_in[0];
    const float* xi = (const float*)d_in[1];
    const float* wr = (const float*)d_in[2];
    const float* wi = (const float*)d_in[3];
    float* out = (float*)d_out;
    sphere_conv_kernel<<<B * L, THREADS>>>(xr, xi, wr, wi, out);
}